// round 2
// baseline (speedup 1.0000x reference)
#include <cuda_runtime.h>
#include <math.h>

#define B 64
#define S 512
#define H 512
#define IN 84
#define NC 100
#define XW 266

#define NCTA 128
#define NTH 256
#define HS 4           // hidden units per CTA
#define NROWS 16       // gate rows per CTA

// ---- static device scratch (no cudaMalloc allowed) ----
__device__ float g_feats[S * IN * B];            // [S][IN][B]  ~11 MB
__device__ float g_hbuf[2 * H * B];              // [2][H][B]   double-buffered h
__device__ float g_lstm[(size_t)B * S * H];      // [B][S][H]   ~67 MB
__device__ unsigned g_ctr;

// SMEM layout (floats)
#define OFF_HT   0                      // h_t  [512][64]
#define OFF_FT   (OFF_HT + 512*64)      // f_t  [84][64]
#define OFF_WH   (OFF_FT + 84*64)       // Wh_t [512][16]
#define OFF_WI   (OFF_WH + 512*16)      // Wi_t [84][16]
#define OFF_G    (OFF_WI + 84*16)       // g_sh [16][64]
#define OFF_RED  (OFF_G + 16*64)        // red  [3][64][16]
#define OFF_CST  (OFF_RED + 3*64*16)    // cst  [4][64]
#define OFF_BIAS (OFF_CST + 4*64)       // bias [16]
#define SMEM_FLOATS (OFF_BIAS + 16)
#define SMEM_BYTES (SMEM_FLOATS * 4)

// ============================================================ reset
__global__ void reset_kernel() {
    int t = blockIdx.x * blockDim.x + threadIdx.x;
    if (t == 0) g_ctr = 0u;
    if (t < H * B) g_hbuf[t] = 0.0f;
}

// ============================================================ preprocessing
// feat[b,s,:] = concat(norm(left pts 91..111), norm(right pts 112..132))
__global__ void prep_kernel(const float* __restrict__ x) {
    int s = blockIdx.x;
    int b = threadIdx.x;
    const float* xp = x + ((size_t)b * S + s) * XW;
    float cx = xp[0], cy = xp[1];
    #pragma unroll
    for (int hnd = 0; hnd < 2; hnd++) {
        int pbase = (hnd == 0) ? 91 : 112;
        float mnx = 1e30f, mxx = -1e30f, mny = 1e30f, mxy = -1e30f;
        #pragma unroll
        for (int p = 0; p < 21; p++) {
            float px = xp[(pbase + p) * 2];
            float py = xp[(pbase + p) * 2 + 1];
            mnx = fminf(mnx, px); mxx = fmaxf(mxx, px);
            mny = fminf(mny, py); mxy = fmaxf(mxy, py);
        }
        float whx = mxx - mnx, why = mxy - mny;
        bool ok = (whx != 0.0f) && (why != 0.0f);
        float sx = ok ? whx : 1.0f;
        float sy = ok ? why : 1.0f;
        #pragma unroll
        for (int p = 0; p < 21; p++) {
            float px = xp[(pbase + p) * 2];
            float py = xp[(pbase + p) * 2 + 1];
            int i0 = hnd * 42 + p * 2;
            g_feats[((size_t)s * IN + i0) * B + b]     = (px - cx) / sx;
            g_feats[((size_t)s * IN + i0 + 1) * B + b] = (py - cy) / sy;
        }
    }
}

// ============================================================ recurrence
#define ACC16(wv, hv) do { \
    acc[0]  = fmaf(wv.x, hv.x, acc[0]);  \
    acc[1]  = fmaf(wv.x, hv.y, acc[1]);  \
    acc[2]  = fmaf(wv.x, hv.z, acc[2]);  \
    acc[3]  = fmaf(wv.x, hv.w, acc[3]);  \
    acc[4]  = fmaf(wv.y, hv.x, acc[4]);  \
    acc[5]  = fmaf(wv.y, hv.y, acc[5]);  \
    acc[6]  = fmaf(wv.y, hv.z, acc[6]);  \
    acc[7]  = fmaf(wv.y, hv.w, acc[7]);  \
    acc[8]  = fmaf(wv.z, hv.x, acc[8]);  \
    acc[9]  = fmaf(wv.z, hv.y, acc[9]);  \
    acc[10] = fmaf(wv.z, hv.z, acc[10]); \
    acc[11] = fmaf(wv.z, hv.w, acc[11]); \
    acc[12] = fmaf(wv.w, hv.x, acc[12]); \
    acc[13] = fmaf(wv.w, hv.y, acc[13]); \
    acc[14] = fmaf(wv.w, hv.z, acc[14]); \
    acc[15] = fmaf(wv.w, hv.w, acc[15]); \
} while (0)

__global__ void __launch_bounds__(NTH, 1)
lstm_kernel(const float* __restrict__ W_ih, const float* __restrict__ W_hh,
            const float* __restrict__ b_ih, const float* __restrict__ b_hh) {
    extern __shared__ float sm[];
    float* h_t   = sm + OFF_HT;
    float* f_t   = sm + OFF_FT;
    float* Wh_t  = sm + OFF_WH;
    float* Wi_t  = sm + OFF_WI;
    float* g_sh  = sm + OFF_G;
    float* red   = sm + OFF_RED;
    float* cst   = sm + OFF_CST;
    float* bias  = sm + OFF_BIAS;

    const int t   = threadIdx.x;
    const int blk = blockIdx.x;
    const int kp  = t >> 6;        // 0..3  K partition
    const int sub = t & 63;
    const int rg  = sub >> 4;      // 0..3  row group (4 rows)
    const int bg  = sub & 15;      // 0..15 batch group (4 batches)

    // ---- one-time weight staging (transposed: [k][r]) ----
    for (int idx = t; idx < NROWS * H; idx += NTH) {
        int r = idx & 15, k = idx >> 4;
        int grow = (r >> 2) * H + blk * HS + (r & 3);   // gate*H + unit
        Wh_t[k * 16 + r] = W_hh[(size_t)grow * H + k];
    }
    for (int idx = t; idx < NROWS * IN; idx += NTH) {
        int r = idx & 15, k = idx >> 4;
        int grow = (r >> 2) * H + blk * HS + (r & 3);
        Wi_t[k * 16 + r] = W_ih[(size_t)grow * IN + k];
    }
    if (t < NROWS) {
        int grow = (t >> 2) * H + blk * HS + (t & 3);
        bias[t] = b_ih[grow] + b_hh[grow];
    }
    for (int idx = t; idx < HS * B; idx += NTH) cst[idx] = 0.0f;
    __syncthreads();

    const float4* wp  = ((const float4*)Wh_t) + rg;  // stride 4 float4 per k
    const float4* wip = ((const float4*)Wi_t) + rg;
    const float4* hp  = ((const float4*)h_t) + bg;   // stride 16 float4 per k
    const float4* fp  = ((const float4*)f_t) + bg;

    for (int s = 0; s < S; s++) {
        const int cur = s & 1, nxt = cur ^ 1;

        // stage h[cur] -> SMEM (contiguous 128 KB)
        {
            const float4* src = (const float4*)&g_hbuf[cur * H * B];
            float4* dst = (float4*)h_t;
            #pragma unroll 4
            for (int idx = t; idx < H * B / 4; idx += NTH) dst[idx] = src[idx];
        }
        // stage feats[s] -> SMEM (contiguous 21 KB)
        {
            const float4* src = (const float4*)&g_feats[(size_t)s * IN * B];
            float4* dst = (float4*)f_t;
            for (int idx = t; idx < IN * B / 4; idx += NTH) dst[idx] = src[idx];
        }
        __syncthreads();

        float acc[16];
        #pragma unroll
        for (int ri = 0; ri < 4; ri++)
            #pragma unroll
            for (int bi = 0; bi < 4; bi++)
                acc[ri * 4 + bi] = (kp == 0) ? bias[rg * 4 + ri] : 0.0f;

        // main recurrence GEMM: K slice [kp*128, kp*128+128)
        const int k0 = kp * 128;
        #pragma unroll 4
        for (int k = k0; k < k0 + 128; k++) {
            float4 hv = hp[k * 16];
            float4 wv = wp[k * 4];
            ACC16(wv, hv);
        }
        // input projection: K slice [kp*21, kp*21+21)
        const int ki0 = kp * 21;
        #pragma unroll 3
        for (int k = ki0; k < ki0 + 21; k++) {
            float4 hv = fp[k * 16];
            float4 wv = wip[k * 4];
            ACC16(wv, hv);
        }

        // reduce across kp partitions
        if (kp > 0) {
            float* rp = &red[((kp - 1) * 64 + sub) * 16];
            #pragma unroll
            for (int i = 0; i < 16; i++) rp[i] = acc[i];
        }
        __syncthreads();
        if (kp == 0) {
            #pragma unroll
            for (int i = 0; i < 16; i++) {
                float v = acc[i]
                        + red[(0 * 64 + sub) * 16 + i]
                        + red[(1 * 64 + sub) * 16 + i]
                        + red[(2 * 64 + sub) * 16 + i];
                int ri = i >> 2, bi = i & 3;
                g_sh[(rg * 4 + ri) * 64 + (bg * 4 + bi)] = v;
            }
        }
        __syncthreads();

        // gate phase: 64 threads, one batch each
        if (t < B) {
            int b = t;
            float hv4[4];
            #pragma unroll
            for (int u = 0; u < 4; u++) {
                float gi = g_sh[(0 + u) * 64 + b];
                float gf = g_sh[(4 + u) * 64 + b];
                float gg = g_sh[(8 + u) * 64 + b];
                float go = g_sh[(12 + u) * 64 + b];
                float i_ = 1.0f / (1.0f + expf(-gi));
                float f_ = 1.0f / (1.0f + expf(-gf));
                float g_ = tanhf(gg);
                float o_ = 1.0f / (1.0f + expf(-go));
                float c = f_ * cst[u * 64 + b] + i_ * g_;
                cst[u * 64 + b] = c;
                float hn = o_ * tanhf(c);
                hv4[u] = hn;
                g_hbuf[nxt * H * B + (blk * HS + u) * B + b] = hn;
            }
            *(float4*)&g_lstm[((size_t)b * S + s) * H + blk * HS] =
                make_float4(hv4[0], hv4[1], hv4[2], hv4[3]);
        }

        // grid barrier (monotonic counter; all 128 CTAs are co-resident)
        if (s != S - 1) {
            __syncthreads();
            if (t == 0) {
                __threadfence();
                atomicAdd(&g_ctr, 1u);
                unsigned target = (unsigned)(s + 1) * NCTA;
                unsigned v;
                do {
                    asm volatile("ld.acquire.gpu.u32 %0, [%1];"
                                 : "=r"(v) : "l"(&g_ctr) : "memory");
                } while (v < target);
            }
            __syncthreads();
        }
    }
}

// ============================================================ attention + FC
__global__ void __launch_bounds__(256)
attn_kernel(const float* __restrict__ attn_w, const float* __restrict__ fc_w,
            const float* __restrict__ fc_b, float* __restrict__ out) {
    __shared__ float s_aw[H];
    __shared__ float s_sc[S];
    __shared__ float s_ctx[H];
    __shared__ float s_red[8];

    int b = blockIdx.x, t = threadIdx.x;
    int lane = t & 31, warp = t >> 5;
    for (int i = t; i < H; i += 256) s_aw[i] = attn_w[i];
    __syncthreads();

    const float* lo = &g_lstm[(size_t)b * S * H];

    // scores[s] = dot(lstm_out[b,s,:], attn_w)
    for (int s = t; s < S; s += 256) {
        const float4* row = (const float4*)&lo[(size_t)s * H];
        const float4* a4  = (const float4*)s_aw;
        float acc = 0.0f;
        #pragma unroll 8
        for (int i = 0; i < H / 4; i++) {
            float4 rv = row[i], av = a4[i];
            acc += rv.x * av.x + rv.y * av.y + rv.z * av.z + rv.w * av.w;
        }
        s_sc[s] = acc;
    }
    __syncthreads();

    // softmax over S
    float m = -1e30f;
    for (int i = t; i < S; i += 256) m = fmaxf(m, s_sc[i]);
    #pragma unroll
    for (int o = 16; o; o >>= 1) m = fmaxf(m, __shfl_xor_sync(0xFFFFFFFFu, m, o));
    if (lane == 0) s_red[warp] = m;
    __syncthreads();
    m = s_red[0];
    #pragma unroll
    for (int i = 1; i < 8; i++) m = fmaxf(m, s_red[i]);
    __syncthreads();

    float sum = 0.0f;
    for (int i = t; i < S; i += 256) {
        float e = expf(s_sc[i] - m);
        s_sc[i] = e;
        sum += e;
    }
    #pragma unroll
    for (int o = 16; o; o >>= 1) sum += __shfl_xor_sync(0xFFFFFFFFu, sum, o);
    if (lane == 0) s_red[warp] = sum;
    __syncthreads();
    float tot = 0.0f;
    #pragma unroll
    for (int i = 0; i < 8; i++) tot += s_red[i];
    float inv = 1.0f / tot;
    for (int i = t; i < S; i += 256) {
        float w = s_sc[i] * inv;
        s_sc[i] = w;
        out[NC * B + b * S + i] = w;   // weights output region
    }
    __syncthreads();

    // ctx[h] = sum_s w[s] * lstm_out[b,s,h]   (each thread: h and h+256)
    {
        float c0 = 0.0f, c1 = 0.0f;
        int h0 = t, h1 = t + 256;
        #pragma unroll 4
        for (int s = 0; s < S; s++) {
            float w = s_sc[s];
            c0 = fmaf(w, lo[(size_t)s * H + h0], c0);
            c1 = fmaf(w, lo[(size_t)s * H + h1], c1);
        }
        s_ctx[h0] = c0;
        s_ctx[h1] = c1;
    }
    __syncthreads();

    // out = ctx @ fc_w.T + fc_b
    if (t < NC) {
        const float4* w4 = (const float4*)&fc_w[(size_t)t * H];
        const float4* c4 = (const float4*)s_ctx;
        float acc = fc_b[t];
        #pragma unroll 8
        for (int i = 0; i < H / 4; i++) {
            float4 wv = w4[i], cv = c4[i];
            acc += wv.x * cv.x + wv.y * cv.y + wv.z * cv.z + wv.w * cv.w;
        }
        out[b * NC + t] = acc;
    }
}

// ============================================================ launch
extern "C" void kernel_launch(void* const* d_in, const int* in_sizes, int n_in,
                              void* d_out, int out_size) {
    const float* x      = (const float*)d_in[0];
    const float* W_ih   = (const float*)d_in[1];
    const float* W_hh   = (const float*)d_in[2];
    const float* b_ih   = (const float*)d_in[3];
    const float* b_hh   = (const float*)d_in[4];
    const float* attn_w = (const float*)d_in[5];
    const float* fc_w   = (const float*)d_in[6];
    const float* fc_b   = (const float*)d_in[7];
    float* out = (float*)d_out;

    cudaFuncSetAttribute(lstm_kernel,
                         cudaFuncAttributeMaxDynamicSharedMemorySize, SMEM_BYTES);

    reset_kernel<<<(H * B + NTH - 1) / NTH, NTH>>>();
    prep_kernel<<<S, B>>>(x);
    lstm_kernel<<<NCTA, NTH, SMEM_BYTES>>>(W_ih, W_hh, b_ih, b_hh);
    attn_kernel<<<B, 256>>>(attn_w, fc_w, fc_b, out);
}

// round 3
// speedup vs baseline: 1.6353x; 1.6353x over previous
#include <cuda_runtime.h>
#include <math.h>

#define B 64
#define S 512
#define H 512
#define IN 84
#define NC 100
#define XW 266
#define HB (H * B)

#define NCTA 128
#define NTH 256

// ---- static device scratch (no cudaMalloc allowed) ----
__device__ float g_feats[S * IN * B];            // [S][IN][B]
__device__ float g_hbuf[2 * HB];                 // [2][H][B]
__device__ float g_lstm[(size_t)B * S * H];      // [B][S][H]
__device__ unsigned g_ctr;

// SMEM layout (float offsets)
#define OFF_HSL  0                        // 8 warp regions x [128][32]
#define OFF_FSL  (OFF_HSL + 8 * 4096)     // 8 warp regions x [21][32]
#define OFF_WH   (OFF_FSL + 8 * 672)      // [512][16] transposed W_hh slice
#define OFF_WI   (OFF_WH + 512 * 16)      // [84][16] transposed W_ih slice
#define OFF_RED  (OFF_WI + 84 * 16)       // [4][16][66] padded partials
#define OFF_BIAS (OFF_RED + 4 * 16 * 66)  // [16]
#define SMEM_FLOATS (OFF_BIAS + 16)
#define SMEM_BYTES (SMEM_FLOATS * 4)

// ---- packed fp32x2 helpers (ptxas won't auto-emit FFMA2) ----
__device__ __forceinline__ unsigned long long bcast2(float x) {
    unsigned long long r;
    unsigned u = __float_as_uint(x);
    asm("mov.b64 %0, {%1, %1};" : "=l"(r) : "r"(u));
    return r;
}
__device__ __forceinline__ void ffma2(unsigned long long& d,
                                      unsigned long long a,
                                      unsigned long long b) {
    asm("fma.rn.f32x2 %0, %1, %2, %0;" : "+l"(d) : "l"(a), "l"(b));
}
__device__ __forceinline__ float2 unpack2(unsigned long long v) {
    unsigned lo, hi;
    asm("mov.b64 {%0, %1}, %2;" : "=r"(lo), "=r"(hi) : "l"(v));
    return make_float2(__uint_as_float(lo), __uint_as_float(hi));
}

__device__ __forceinline__ float sigf(float x) {
    return __fdividef(1.0f, 1.0f + __expf(-x));
}
__device__ __forceinline__ float tanhfast(float x) {
    return __fdividef(2.0f, 1.0f + __expf(-2.0f * x)) - 1.0f;
}

// ============================================================ reset
__global__ void reset_kernel() {
    int t = blockIdx.x * blockDim.x + threadIdx.x;
    if (t == 0) g_ctr = 0u;
    if (t < HB) g_hbuf[t] = 0.0f;
}

// ============================================================ preprocessing
__global__ void prep_kernel(const float* __restrict__ x) {
    int s = blockIdx.x;
    int b = threadIdx.x;
    const float* xp = x + ((size_t)b * S + s) * XW;
    float cx = xp[0], cy = xp[1];
    #pragma unroll
    for (int hnd = 0; hnd < 2; hnd++) {
        int pbase = (hnd == 0) ? 91 : 112;
        float mnx = 1e30f, mxx = -1e30f, mny = 1e30f, mxy = -1e30f;
        #pragma unroll
        for (int p = 0; p < 21; p++) {
            float px = xp[(pbase + p) * 2];
            float py = xp[(pbase + p) * 2 + 1];
            mnx = fminf(mnx, px); mxx = fmaxf(mxx, px);
            mny = fminf(mny, py); mxy = fmaxf(mxy, py);
        }
        float whx = mxx - mnx, why = mxy - mny;
        bool ok = (whx != 0.0f) && (why != 0.0f);
        float sx = ok ? whx : 1.0f;
        float sy = ok ? why : 1.0f;
        #pragma unroll
        for (int p = 0; p < 21; p++) {
            float px = xp[(pbase + p) * 2];
            float py = xp[(pbase + p) * 2 + 1];
            int i0 = hnd * 42 + p * 2;
            g_feats[((size_t)s * IN + i0) * B + b]     = (px - cx) / sx;
            g_feats[((size_t)s * IN + i0 + 1) * B + b] = (py - cy) / sy;
        }
    }
}

// ============================================================ recurrence
// 8 warps: warp w -> kp = w>>1 (K partition of 128), bh = w&1 (batch half of 32)
// thread tile: 8 rows (rg*8..) x 2 batches (bg*2..), acc packed over row pairs.
#define FMA8(wa, wb, h0, h1) do {          \
    ffma2(acc[0], wa.x, h0);               \
    ffma2(acc[1], wa.x, h1);               \
    ffma2(acc[2], wa.y, h0);               \
    ffma2(acc[3], wa.y, h1);               \
    ffma2(acc[4], wb.x, h0);               \
    ffma2(acc[5], wb.x, h1);               \
    ffma2(acc[6], wb.y, h0);               \
    ffma2(acc[7], wb.y, h1);               \
} while (0)

__global__ void __launch_bounds__(NTH, 1)
lstm_kernel(const float* __restrict__ W_ih, const float* __restrict__ W_hh,
            const float* __restrict__ b_ih, const float* __restrict__ b_hh) {
    extern __shared__ float sm[];
    float* Wh_t = sm + OFF_WH;
    float* Wi_t = sm + OFF_WI;
    float* red  = sm + OFF_RED;
    float* bias = sm + OFF_BIAS;

    const int t    = threadIdx.x;
    const int blk  = blockIdx.x;
    const int lane = t & 31;
    const int wrp  = t >> 5;
    const int kp   = wrp >> 1;     // 0..3
    const int bh   = wrp & 1;      // 0..1
    const int rg   = lane >> 4;    // 0..1  (8-row group)
    const int bg   = lane & 15;    // 0..15 (2-batch group)

    float* h_sl = sm + OFF_HSL + ((kp * 2 + bh) << 12);   // [128][32]
    float* f_sl = sm + OFF_FSL + (kp * 2 + bh) * 672;     // [21][32]

    // ---- one-time weight staging, transposed [k][16 rows] ----
    for (int idx = t; idx < 16 * H; idx += NTH) {
        int r = idx & 15, k = idx >> 4;
        int grow = (r >> 2) * H + blk * 4 + (r & 3);
        Wh_t[k * 16 + r] = W_hh[(size_t)grow * H + k];
    }
    for (int idx = t; idx < 16 * IN; idx += NTH) {
        int r = idx & 15, k = idx >> 4;
        int grow = (r >> 2) * H + blk * 4 + (r & 3);
        Wi_t[k * 16 + r] = W_ih[(size_t)grow * IN + k];
    }
    if (t < 16) {
        int grow = (t >> 2) * H + blk * 4 + (t & 3);
        bias[t] = b_ih[grow] + b_hh[grow];
    }
    __syncthreads();

    // per-lane staging offsets (chunk = 16 k-rows)
    const int gbl = (lane >> 3) * B + (lane & 7) * 4;    // gmem (rows of 64 floats)
    const int sbl = (lane >> 3) * 32 + (lane & 7) * 4;   // smem (rows of 32 floats)
    const float* hsrc_base = g_hbuf + kp * 128 * B + bh * 32;
    const float* fsrc_base = g_feats + (size_t)kp * 21 * B + bh * 32;

    // reducer mapping: thread -> (unit, batch)
    const int ru = t >> 6;
    const int rb = t & 63;
    const int ubase = blk * 4 + ru;
    float creg = 0.0f;

    for (int s = 0; s < S; s++) {
        const int cur = s & 1, nxt = cur ^ 1;
        const float* hsrc = hsrc_base + cur * HB;

        unsigned long long acc[8];
        #pragma unroll
        for (int i = 0; i < 8; i++) acc[i] = 0ull;

        // feats LDG issue early (arrive during h chunks)
        float freg[21];
        {
            const float* fs = fsrc_base + (size_t)s * IN * B;
            #pragma unroll
            for (int i = 0; i < 21; i++) freg[i] = fs[i * B + lane];
        }

        // ---- pipelined h staging + GEMM (warp-private slice, 8 chunks x 16 k) ----
        float4 bufA[4], bufB[4];
        #pragma unroll
        for (int j = 0; j < 4; j++)
            bufA[j] = *(const float4*)(hsrc + j * 4 * B + gbl);

        #pragma unroll 2
        for (int ch = 0; ch < 8; ch++) {
            float4* cb = (ch & 1) ? bufB : bufA;
            float4* nb = (ch & 1) ? bufA : bufB;
            if (ch < 7) {
                #pragma unroll
                for (int j = 0; j < 4; j++)
                    nb[j] = *(const float4*)(hsrc + (ch + 1) * 16 * B + j * 4 * B + gbl);
            }
            #pragma unroll
            for (int j = 0; j < 4; j++)
                *(float4*)(h_sl + ch * 512 + j * 128 + sbl) = cb[j];
            __syncwarp();

            const float* hk = h_sl + ch * 512 + bg * 2;
            const ulonglong2* wk =
                (const ulonglong2*)(Wh_t + (kp * 128 + ch * 16) * 16 + rg * 8);
            #pragma unroll 4
            for (int k = 0; k < 16; k++) {
                float2 hv = *(const float2*)(hk + k * 32);
                ulonglong2 wa = wk[k * 4];
                ulonglong2 wb = wk[k * 4 + 1];
                unsigned long long h0 = bcast2(hv.x);
                unsigned long long h1 = bcast2(hv.y);
                FMA8(wa, wb, h0, h1);
            }
        }

        // ---- input projection (21 k, warp-private slice) ----
        #pragma unroll
        for (int i = 0; i < 21; i++) f_sl[i * 32 + lane] = freg[i];
        __syncwarp();
        {
            const float* fk = f_sl + bg * 2;
            const ulonglong2* wk = (const ulonglong2*)(Wi_t + kp * 21 * 16 + rg * 8);
            #pragma unroll 3
            for (int k = 0; k < 21; k++) {
                float2 hv = *(const float2*)(fk + k * 32);
                ulonglong2 wa = wk[k * 4];
                ulonglong2 wb = wk[k * 4 + 1];
                unsigned long long h0 = bcast2(hv.x);
                unsigned long long h1 = bcast2(hv.y);
                FMA8(wa, wb, h0, h1);
            }
        }

        // ---- K-partition partials to SMEM (padded stride 66) ----
        {
            const int bb = bh * 32 + bg * 2;
            #pragma unroll
            for (int rp = 0; rp < 4; rp++) {
                #pragma unroll
                for (int b2 = 0; b2 < 2; b2++) {
                    float2 v = unpack2(acc[rp * 2 + b2]);
                    int r0 = rg * 8 + rp * 2;
                    red[(kp * 16 + r0) * 66 + bb + b2]     = v.x;
                    red[(kp * 16 + r0 + 1) * 66 + bb + b2] = v.y;
                }
            }
        }
        __syncthreads();

        // ---- reduce + gates: thread = (unit ru, batch rb), c-state in register ----
        {
            float g4[4];
            #pragma unroll
            for (int gt = 0; gt < 4; gt++) {
                int r = gt * 4 + ru;
                float v = bias[r];
                #pragma unroll
                for (int k4 = 0; k4 < 4; k4++)
                    v += red[(k4 * 16 + r) * 66 + rb];
                g4[gt] = v;
            }
            float i_ = sigf(g4[0]);
            float f_ = sigf(g4[1]);
            float gg = tanhfast(g4[2]);
            float o_ = sigf(g4[3]);
            creg = f_ * creg + i_ * gg;
            float hn = o_ * tanhfast(creg);
            g_hbuf[nxt * HB + ubase * B + rb] = hn;
            g_lstm[((size_t)rb * S + s) * H + ubase] = hn;
        }

        // ---- grid barrier (128 co-resident CTAs, monotonic counter) ----
        if (s != S - 1) {
            __syncthreads();
            if (t == 0) {
                __threadfence();
                atomicAdd(&g_ctr, 1u);
                unsigned target = (unsigned)(s + 1) * NCTA;
                unsigned v;
                do {
                    asm volatile("ld.acquire.gpu.u32 %0, [%1];"
                                 : "=r"(v) : "l"(&g_ctr) : "memory");
                } while (v < target);
            }
            __syncthreads();
        }
    }
}

// ============================================================ attention + FC
__global__ void __launch_bounds__(256)
attn_kernel(const float* __restrict__ attn_w, const float* __restrict__ fc_w,
            const float* __restrict__ fc_b, float* __restrict__ out) {
    __shared__ float s_aw[H];
    __shared__ float s_sc[S];
    __shared__ float s_ctx[H];
    __shared__ float s_red[8];

    int b = blockIdx.x, t = threadIdx.x;
    int lane = t & 31, warp = t >> 5;
    for (int i = t; i < H; i += 256) s_aw[i] = attn_w[i];
    __syncthreads();

    const float* lo = &g_lstm[(size_t)b * S * H];

    for (int s = t; s < S; s += 256) {
        const float4* row = (const float4*)&lo[(size_t)s * H];
        const float4* a4  = (const float4*)s_aw;
        float acc = 0.0f;
        #pragma unroll 8
        for (int i = 0; i < H / 4; i++) {
            float4 rv = row[i], av = a4[i];
            acc += rv.x * av.x + rv.y * av.y + rv.z * av.z + rv.w * av.w;
        }
        s_sc[s] = acc;
    }
    __syncthreads();

    float m = -1e30f;
    for (int i = t; i < S; i += 256) m = fmaxf(m, s_sc[i]);
    #pragma unroll
    for (int o = 16; o; o >>= 1) m = fmaxf(m, __shfl_xor_sync(0xFFFFFFFFu, m, o));
    if (lane == 0) s_red[warp] = m;
    __syncthreads();
    m = s_red[0];
    #pragma unroll
    for (int i = 1; i < 8; i++) m = fmaxf(m, s_red[i]);
    __syncthreads();

    float sum = 0.0f;
    for (int i = t; i < S; i += 256) {
        float e = expf(s_sc[i] - m);
        s_sc[i] = e;
        sum += e;
    }
    #pragma unroll
    for (int o = 16; o; o >>= 1) sum += __shfl_xor_sync(0xFFFFFFFFu, sum, o);
    if (lane == 0) s_red[warp] = sum;
    __syncthreads();
    float tot = 0.0f;
    #pragma unroll
    for (int i = 0; i < 8; i++) tot += s_red[i];
    float inv = 1.0f / tot;
    for (int i = t; i < S; i += 256) {
        float w = s_sc[i] * inv;
        s_sc[i] = w;
        out[NC * B + b * S + i] = w;
    }
    __syncthreads();

    {
        float c0 = 0.0f, c1 = 0.0f;
        int h0 = t, h1 = t + 256;
        #pragma unroll 4
        for (int s = 0; s < S; s++) {
            float w = s_sc[s];
            c0 = fmaf(w, lo[(size_t)s * H + h0], c0);
            c1 = fmaf(w, lo[(size_t)s * H + h1], c1);
        }
        s_ctx[h0] = c0;
        s_ctx[h1] = c1;
    }
    __syncthreads();

    if (t < NC) {
        const float4* w4 = (const float4*)&fc_w[(size_t)t * H];
        const float4* c4 = (const float4*)s_ctx;
        float acc = fc_b[t];
        #pragma unroll 8
        for (int i = 0; i < H / 4; i++) {
            float4 wv = w4[i], cv = c4[i];
            acc += wv.x * cv.x + wv.y * cv.y + wv.z * cv.z + wv.w * cv.w;
        }
        out[b * NC + t] = acc;
    }
}

// ============================================================ launch
extern "C" void kernel_launch(void* const* d_in, const int* in_sizes, int n_in,
                              void* d_out, int out_size) {
    const float* x      = (const float*)d_in[0];
    const float* W_ih   = (const float*)d_in[1];
    const float* W_hh   = (const float*)d_in[2];
    const float* b_ih   = (const float*)d_in[3];
    const float* b_hh   = (const float*)d_in[4];
    const float* attn_w = (const float*)d_in[5];
    const float* fc_w   = (const float*)d_in[6];
    const float* fc_b   = (const float*)d_in[7];
    float* out = (float*)d_out;

    cudaFuncSetAttribute(lstm_kernel,
                         cudaFuncAttributeMaxDynamicSharedMemorySize, SMEM_BYTES);

    reset_kernel<<<(HB + NTH - 1) / NTH, NTH>>>();
    prep_kernel<<<S, B>>>(x);
    lstm_kernel<<<NCTA, NTH, SMEM_BYTES>>>(W_ih, W_hh, b_ih, b_hh);
    attn_kernel<<<B, 256>>>(attn_w, fc_w, fc_b, out);
}

// round 4
// speedup vs baseline: 2.0308x; 1.2418x over previous
#include <cuda_runtime.h>
#include <math.h>

#define B 64
#define S 512
#define H 512
#define IN 84
#define NC 100
#define XW 266
#define HB (H * B)

#define NCTA 128
#define NTH 256

// ---- static device scratch ----
__device__ float g_feats[S * IN * B];              // [S][IN][B]
__device__ float g_hbuf[2 * HB];                   // [2][H][B]
__device__ float g_lstm[(size_t)S * H * B];        // [S][H][B]
__device__ float g_sc[S * B];                      // [S][B] scores -> weights
__device__ float g_ctx[H * B];                     // [H][B]
__device__ unsigned g_ctr;

// ---- SMEM layout (float offsets) ----
#define OFF_H    0                         // h   [512][64]   131072 B
#define OFF_F    (OFF_H + 512 * 64)        // f   [84][64]    21504 B
#define OFF_WH   (OFF_F + 84 * 64)         // WhT [512][16]
#define OFF_WI   (OFF_WH + 512 * 16)       // WiT [84][16]
#define OFF_RED  (OFF_WI + 84 * 16)        // red [8][16][66]
#define OFF_BIAS (OFF_RED + 8 * 16 * 66)   // [16]
#define OFF_END  (OFF_BIAS + 16)
#define OFF_MBAR_B (OFF_END * 4)           // byte offset, 8-aligned
#define NMBAR 9
#define SMEM_BYTES (OFF_MBAR_B + NMBAR * 8)

// ---- packed fp32x2 helpers ----
__device__ __forceinline__ unsigned long long bcast2(float x) {
    unsigned long long r;
    unsigned u = __float_as_uint(x);
    asm("mov.b64 %0, {%1, %1};" : "=l"(r) : "r"(u));
    return r;
}
__device__ __forceinline__ void ffma2(unsigned long long& d,
                                      unsigned long long a,
                                      unsigned long long b) {
    asm("fma.rn.f32x2 %0, %1, %2, %0;" : "+l"(d) : "l"(a), "l"(b));
}
__device__ __forceinline__ float2 unpack2(unsigned long long v) {
    unsigned lo, hi;
    asm("mov.b64 {%0, %1}, %2;" : "=r"(lo), "=r"(hi) : "l"(v));
    return make_float2(__uint_as_float(lo), __uint_as_float(hi));
}
__device__ __forceinline__ float sigf(float x) {
    return __fdividef(1.0f, 1.0f + __expf(-x));
}
__device__ __forceinline__ float tanhfast(float x) {
    return __fdividef(2.0f, 1.0f + __expf(-2.0f * x)) - 1.0f;
}

// ---- mbarrier / bulk-copy helpers ----
__device__ __forceinline__ unsigned smem_u32(const void* p) {
    return (unsigned)__cvta_generic_to_shared(p);
}
__device__ __forceinline__ void mbar_init(unsigned a, unsigned cnt) {
    asm volatile("mbarrier.init.shared.b64 [%0], %1;" :: "r"(a), "r"(cnt) : "memory");
}
__device__ __forceinline__ void mbar_expect(unsigned a, unsigned bytes) {
    asm volatile("mbarrier.arrive.expect_tx.shared.b64 _, [%0], %1;"
                 :: "r"(a), "r"(bytes) : "memory");
}
__device__ __forceinline__ void bulk_g2s(unsigned dst, const void* src,
                                         unsigned bytes, unsigned mbar) {
    asm volatile(
        "cp.async.bulk.shared::cluster.global.mbarrier::complete_tx::bytes "
        "[%0], [%1], %2, [%3];"
        :: "r"(dst), "l"(src), "r"(bytes), "r"(mbar) : "memory");
}
__device__ __forceinline__ void mbar_wait(unsigned a, unsigned parity) {
    asm volatile(
        "{\n\t.reg .pred P;\n\t"
        "W%=:\n\t"
        "mbarrier.try_wait.parity.shared.b64 P, [%0], %1, 0x989680;\n\t"
        "@P bra D%=;\n\t"
        "bra W%=;\n\t"
        "D%=:\n\t}"
        :: "r"(a), "r"(parity) : "memory");
}

// ============================================================ reset
__global__ void reset_kernel() {
    int t = blockIdx.x * blockDim.x + threadIdx.x;
    if (t == 0) g_ctr = 0u;
    if (t < HB) g_hbuf[t] = 0.0f;
}

// ============================================================ preprocessing
__global__ void prep_kernel(const float* __restrict__ x) {
    int s = blockIdx.x;
    int b = threadIdx.x;
    const float* xp = x + ((size_t)b * S + s) * XW;
    float cx = xp[0], cy = xp[1];
    #pragma unroll
    for (int hnd = 0; hnd < 2; hnd++) {
        int pbase = (hnd == 0) ? 91 : 112;
        float mnx = 1e30f, mxx = -1e30f, mny = 1e30f, mxy = -1e30f;
        #pragma unroll
        for (int p = 0; p < 21; p++) {
            float px = xp[(pbase + p) * 2];
            float py = xp[(pbase + p) * 2 + 1];
            mnx = fminf(mnx, px); mxx = fmaxf(mxx, px);
            mny = fminf(mny, py); mxy = fmaxf(mxy, py);
        }
        float whx = mxx - mnx, why = mxy - mny;
        bool ok = (whx != 0.0f) && (why != 0.0f);
        float sx = ok ? whx : 1.0f;
        float sy = ok ? why : 1.0f;
        #pragma unroll
        for (int p = 0; p < 21; p++) {
            float px = xp[(pbase + p) * 2];
            float py = xp[(pbase + p) * 2 + 1];
            int i0 = hnd * 42 + p * 2;
            g_feats[((size_t)s * IN + i0) * B + b]     = (px - cx) / sx;
            g_feats[((size_t)s * IN + i0 + 1) * B + b] = (py - cy) / sy;
        }
    }
}

// ============================================================ recurrence
// 8 warps, warp w = K-chunk kp (64 k each). Thread tile: 8 rows x 4 batches.
// lanes: rg = lane>>4 (2 row groups of 8), bg = lane&15 (16 batch groups of 4)
#define STEP_K(hv, wa, wb) do {                                   \
    unsigned long long hb0 = bcast2(hv.x);                        \
    unsigned long long hb1 = bcast2(hv.y);                        \
    unsigned long long hb2 = bcast2(hv.z);                        \
    unsigned long long hb3 = bcast2(hv.w);                        \
    ffma2(acc[0],  wa.x, hb0); ffma2(acc[1],  wa.x, hb1);         \
    ffma2(acc[2],  wa.x, hb2); ffma2(acc[3],  wa.x, hb3);         \
    ffma2(acc[4],  wa.y, hb0); ffma2(acc[5],  wa.y, hb1);         \
    ffma2(acc[6],  wa.y, hb2); ffma2(acc[7],  wa.y, hb3);         \
    ffma2(acc[8],  wb.x, hb0); ffma2(acc[9],  wb.x, hb1);         \
    ffma2(acc[10], wb.x, hb2); ffma2(acc[11], wb.x, hb3);         \
    ffma2(acc[12], wb.y, hb0); ffma2(acc[13], wb.y, hb1);         \
    ffma2(acc[14], wb.y, hb2); ffma2(acc[15], wb.y, hb3);         \
} while (0)

__global__ void __launch_bounds__(NTH, 1)
lstm_kernel(const float* __restrict__ W_ih, const float* __restrict__ W_hh,
            const float* __restrict__ b_ih, const float* __restrict__ b_hh) {
    extern __shared__ float sm[];
    float* h_sm = sm + OFF_H;
    float* f_sm = sm + OFF_F;
    float* Wh_t = sm + OFF_WH;
    float* Wi_t = sm + OFF_WI;
    float* red  = sm + OFF_RED;
    float* bias = sm + OFF_BIAS;

    const int t    = threadIdx.x;
    const int blk  = blockIdx.x;
    const int lane = t & 31;
    const int kp   = t >> 5;       // 0..7 K chunk
    const int rg   = lane >> 4;    // 0..1
    const int bg   = lane & 15;    // 0..15

    const unsigned smem_base = smem_u32(sm);
    const unsigned mbar0 = smem_base + OFF_MBAR_B;
    const unsigned h_dst = smem_base + OFF_H * 4;
    const unsigned f_dst = smem_base + OFF_F * 4;

    // ---- one-time staging ----
    for (int idx = t; idx < 16 * H; idx += NTH) {
        int r = idx & 15, k = idx >> 4;
        int grow = (r >> 2) * H + blk * 4 + (r & 3);
        Wh_t[k * 16 + r] = W_hh[(size_t)grow * H + k];
    }
    for (int idx = t; idx < 16 * IN; idx += NTH) {
        int r = idx & 15, k = idx >> 4;
        int grow = (r >> 2) * H + blk * 4 + (r & 3);
        Wi_t[k * 16 + r] = W_ih[(size_t)grow * IN + k];
    }
    if (t < 16) {
        int grow = (t >> 2) * H + blk * 4 + (t & 3);
        bias[t] = b_ih[grow] + b_hh[grow];
    }
    if (t == 0) {
        #pragma unroll
        for (int i = 0; i < NMBAR; i++) mbar_init(mbar0 + i * 8, 1);
    }
    __syncthreads();

    // feats K slice for this warp
    const int foff = kp * 10 + (kp < 4 ? kp : 4);
    const int fcnt = (kp < 4) ? 11 : 10;

    // gate-phase mapping
    const int ru = t >> 6;          // unit 0..3
    const int rb = t & 63;          // batch
    const int ubase = blk * 4 + ru;
    float creg = 0.0f;

    for (int s = 0; s < S; s++) {
        const int cur = s & 1, nxt = cur ^ 1;
        const unsigned par = (unsigned)(s & 1);

        // ---- issue async bulk copies (t0) ----
        if (t == 0) {
            asm volatile("fence.proxy.async;" ::: "memory");
            const float* hsrc = g_hbuf + cur * HB;
            #pragma unroll
            for (int c = 0; c < 8; c++) {
                mbar_expect(mbar0 + c * 8, 16384u);
                bulk_g2s(h_dst + c * 16384u, hsrc + c * 4096, 16384u,
                         mbar0 + c * 8);
            }
            mbar_expect(mbar0 + 8 * 8, IN * B * 4u);
            bulk_g2s(f_dst, g_feats + (size_t)s * IN * B, IN * B * 4u,
                     mbar0 + 8 * 8);
        }

        unsigned long long acc[16];
        #pragma unroll
        for (int i = 0; i < 16; i++) acc[i] = 0ull;

        // ---- recurrence GEMM on own chunk ----
        mbar_wait(mbar0 + kp * 8, par);
        {
            const int k0 = kp * 64;
            #pragma unroll 8
            for (int k = k0; k < k0 + 64; k++) {
                float4 hv = *(const float4*)(h_sm + k * 64 + bg * 4);
                ulonglong2 wa = *(const ulonglong2*)(Wh_t + k * 16 + rg * 8);
                ulonglong2 wb = *(const ulonglong2*)(Wh_t + k * 16 + rg * 8 + 4);
                STEP_K(hv, wa, wb);
            }
        }

        // ---- input projection on own feats slice ----
        mbar_wait(mbar0 + 8 * 8, par);
        {
            #pragma unroll 2
            for (int k = foff; k < foff + fcnt; k++) {
                float4 hv = *(const float4*)(f_sm + k * 64 + bg * 4);
                ulonglong2 wa = *(const ulonglong2*)(Wi_t + k * 16 + rg * 8);
                ulonglong2 wb = *(const ulonglong2*)(Wi_t + k * 16 + rg * 8 + 4);
                STEP_K(hv, wa, wb);
            }
        }

        // ---- write partials ----
        {
            #pragma unroll
            for (int rp = 0; rp < 4; rp++) {
                int r = rg * 8 + rp * 2;
                #pragma unroll
                for (int j = 0; j < 4; j++) {
                    float2 v = unpack2(acc[rp * 4 + j]);
                    red[(kp * 16 + r) * 66 + bg * 4 + j]     = v.x;
                    red[(kp * 16 + r + 1) * 66 + bg * 4 + j] = v.y;
                }
            }
        }
        __syncthreads();

        // ---- reduce + gates ----
        {
            float g4[4];
            #pragma unroll
            for (int gt = 0; gt < 4; gt++) {
                int r = gt * 4 + ru;
                float v = bias[r];
                #pragma unroll
                for (int p = 0; p < 8; p++)
                    v += red[(p * 16 + r) * 66 + rb];
                g4[gt] = v;
            }
            float i_ = sigf(g4[0]);
            float f_ = sigf(g4[1]);
            float gg = tanhfast(g4[2]);
            float o_ = sigf(g4[3]);
            creg = f_ * creg + i_ * gg;
            float hn = o_ * tanhfast(creg);
            g_hbuf[nxt * HB + ubase * B + rb] = hn;
            g_lstm[((size_t)s * H + ubase) * B + rb] = hn;
        }

        // ---- grid barrier ----
        if (s != S - 1) {
            __syncthreads();
            if (t == 0) {
                __threadfence();
                atomicAdd(&g_ctr, 1u);
                unsigned target = (unsigned)(s + 1) * NCTA;
                unsigned v;
                do {
                    asm volatile("ld.acquire.gpu.u32 %0, [%1];"
                                 : "=r"(v) : "l"(&g_ctr) : "memory");
                } while (v < target);
            }
            __syncthreads();
        }
    }
}

// ============================================================ attention
// scores[s][b] = sum_h attn_w[h] * L[s][h][b]
__global__ void __launch_bounds__(256)
scores_kernel(const float* __restrict__ attn_w) {
    __shared__ float aw[H];
    __shared__ float part[4 * 64];
    int t = threadIdx.x, c = blockIdx.x;
    int strip = t >> 6, b = t & 63;
    for (int i = t; i < H; i += 256) aw[i] = attn_w[i];
    __syncthreads();
    for (int s4 = 0; s4 < 4; s4++) {
        int s = c * 4 + s4;
        const float* Ls = g_lstm + (size_t)s * H * B;
        float acc = 0.0f;
        #pragma unroll 4
        for (int h = strip * 128; h < strip * 128 + 128; h++)
            acc = fmaf(aw[h], Ls[h * B + b], acc);
        part[strip * 64 + b] = acc;
        __syncthreads();
        if (strip == 0)
            g_sc[s * B + b] = part[b] + part[64 + b] + part[128 + b] + part[192 + b];
        __syncthreads();
    }
}

__global__ void __launch_bounds__(256)
softmax_kernel(float* __restrict__ out) {
    __shared__ float s_red[8];
    int b = blockIdx.x, t = threadIdx.x;
    int lane = t & 31, warp = t >> 5;
    float v[2];
    v[0] = g_sc[t * B + b];
    v[1] = g_sc[(t + 256) * B + b];
    float m = fmaxf(v[0], v[1]);
    #pragma unroll
    for (int o = 16; o; o >>= 1) m = fmaxf(m, __shfl_xor_sync(~0u, m, o));
    if (lane == 0) s_red[warp] = m;
    __syncthreads();
    m = s_red[0];
    #pragma unroll
    for (int i = 1; i < 8; i++) m = fmaxf(m, s_red[i]);
    __syncthreads();
    float e0 = expf(v[0] - m), e1 = expf(v[1] - m);
    float sum = e0 + e1;
    #pragma unroll
    for (int o = 16; o; o >>= 1) sum += __shfl_xor_sync(~0u, sum, o);
    if (lane == 0) s_red[warp] = sum;
    __syncthreads();
    float tot = 0.0f;
    #pragma unroll
    for (int i = 0; i < 8; i++) tot += s_red[i];
    float inv = 1.0f / tot;
    float w0 = e0 * inv, w1 = e1 * inv;
    g_sc[t * B + b] = w0;
    g_sc[(t + 256) * B + b] = w1;
    out[NC * B + b * S + t] = w0;
    out[NC * B + b * S + t + 256] = w1;
}

// ctx[h][b] = sum_s w[s][b] * L[s][h][b]
__global__ void __launch_bounds__(256)
ctx_kernel() {
    int t = threadIdx.x, c = blockIdx.x;
    int hl = t >> 6, b = t & 63;
    int h = c * 4 + hl;
    float acc = 0.0f;
    const float* Lb = g_lstm + (size_t)h * B + b;
    #pragma unroll 4
    for (int s = 0; s < S; s++)
        acc = fmaf(g_sc[s * B + b], Lb[(size_t)s * H * B], acc);
    g_ctx[h * B + b] = acc;
}

__global__ void __launch_bounds__(64)
fc_kernel(const float* __restrict__ fc_w, const float* __restrict__ fc_b,
          float* __restrict__ out) {
    __shared__ float wrow[H];
    int c = blockIdx.x, b = threadIdx.x;
    for (int i = b; i < H; i += 64) wrow[i] = fc_w[(size_t)c * H + i];
    __syncthreads();
    float acc = fc_b[c];
    #pragma unroll 8
    for (int h = 0; h < H; h++)
        acc = fmaf(wrow[h], g_ctx[h * B + b], acc);
    out[b * NC + c] = acc;
}

// ============================================================ launch
extern "C" void kernel_launch(void* const* d_in, const int* in_sizes, int n_in,
                              void* d_out, int out_size) {
    const float* x      = (const float*)d_in[0];
    const float* W_ih   = (const float*)d_in[1];
    const float* W_hh   = (const float*)d_in[2];
    const float* b_ih   = (const float*)d_in[3];
    const float* b_hh   = (const float*)d_in[4];
    const float* attn_w = (const float*)d_in[5];
    const float* fc_w   = (const float*)d_in[6];
    const float* fc_b   = (const float*)d_in[7];
    float* out = (float*)d_out;

    cudaFuncSetAttribute(lstm_kernel,
                         cudaFuncAttributeMaxDynamicSharedMemorySize, SMEM_BYTES);

    reset_kernel<<<(HB + NTH - 1) / NTH, NTH>>>();
    prep_kernel<<<S, B>>>(x);
    lstm_kernel<<<NCTA, NTH, SMEM_BYTES>>>(W_ih, W_hh, b_ih, b_hh);
    scores_kernel<<<S / 4, 256>>>(attn_w);
    softmax_kernel<<<B, 256>>>(out);
    ctx_kernel<<<H / 4, 256>>>();
    fc_kernel<<<NC, 64>>>(fc_w, fc_b, out);
}